// round 14
// baseline (speedup 1.0000x reference)
#include <cuda_runtime.h>
#include <cuda_bf16.h>
#include <math.h>
#include <stdint.h>

#define NSQ 12
#define NTOK 32768
#define TLEN 8192

__device__ float  g_M[8*65536];
__device__ float  g_fsp[NSQ+1][8][8];
__device__ float  g_inv_s;
__device__ float2 g_lam[64];
__device__ float2 g_lamL[64];
__device__ float  g_pi[NTOK*8];
__device__ float  g_v[(size_t)NTOK*128];
__device__ float  g_zscr[(size_t)NTOK*128];
__device__ float  g_y21[(size_t)NTOK*128];
__device__ float2 g_carry[4*64*64];
__device__ float2 g_Cin[4*64*64];
// spectral split images: [buf 2][m 8][img 2][n 256][kp 128] u32 (bf16x2, k-pairs)
__device__ uint32_t g_simg[2][8][2][32768];
// W split images: [mix 3][m 8][img 2][kc 4][n 128][kp 16] u32 (bf16x2)
__device__ uint32_t g_Wsw[3*8*2*4*2048];

__device__ __forceinline__ uint32_t bfsplit_hi(float a, float b) {
    __nv_bfloat16 h0 = __float2bfloat16(a), h1 = __float2bfloat16(b);
    return (uint32_t)__bfloat16_as_ushort(h0) | ((uint32_t)__bfloat16_as_ushort(h1) << 16);
}
__device__ __forceinline__ uint32_t bfsplit_lo(float a, float b) {
    __nv_bfloat16 h0 = __float2bfloat16(a), h1 = __float2bfloat16(b);
    float r0 = a - __bfloat162float(h0), r1 = b - __bfloat162float(h1);
    __nv_bfloat16 l0 = __float2bfloat16(r0), l1 = __float2bfloat16(r1);
    return (uint32_t)__bfloat16_as_ushort(l0) | ((uint32_t)__bfloat16_as_ushort(l1) << 16);
}
__device__ __forceinline__ void mma_bf16(float* c, const uint32_t* a, const uint32_t* b) {
    asm volatile(
        "mma.sync.aligned.m16n8k16.row.col.f32.bf16.bf16.f32 "
        "{%0,%1,%2,%3},{%4,%5,%6,%7},{%8,%9},{%0,%1,%2,%3};"
        : "+f"(c[0]), "+f"(c[1]), "+f"(c[2]), "+f"(c[3])
        : "r"(a[0]), "r"(a[1]), "r"(a[2]), "r"(a[3]), "r"(b[0]), "r"(b[1]));
}
__device__ __forceinline__ void cp_async16(void* smem_dst, const void* gsrc) {
    unsigned sa = (unsigned)__cvta_generic_to_shared(smem_dst);
    asm volatile("cp.async.cg.shared.global [%0], [%1], 16;" :: "r"(sa), "l"(gsrc) : "memory");
}
#define CP_COMMIT() asm volatile("cp.async.commit_group;" ::: "memory")
#define CP_WAIT0()  asm volatile("cp.async.wait_group 0;" ::: "memory")
__device__ __forceinline__ void ldsm_x4(uint32_t& r0, uint32_t& r1, uint32_t& r2,
                                        uint32_t& r3, uint32_t addr) {
    asm volatile("ldmatrix.sync.aligned.m8n8.x4.shared.b16 {%0,%1,%2,%3},[%4];"
        : "=r"(r0), "=r"(r1), "=r"(r2), "=r"(r3) : "r"(addr));
}
__device__ __forceinline__ void ldsm_x2(uint32_t& r0, uint32_t& r1, uint32_t addr) {
    asm volatile("ldmatrix.sync.aligned.m8n8.x2.shared.b16 {%0,%1},[%2];"
        : "=r"(r0), "=r"(r1) : "r"(addr));
}

// -------- 1) assemble K_raw per expert (256x256) --------
__global__ __launch_bounds__(256) void prep_kernel(
    const float* __restrict__ rho_raw, const float* __restrict__ theta,
    const float* __restrict__ K12, const float* __restrict__ K21,
    const float* __restrict__ K22)
{
    __shared__ float sc[64], ss[64];
    int m = blockIdx.x;
    if (threadIdx.x < 64) {
        int t = threadIdx.x;
        float rho = (1.0f/(1.0f+expf(-rho_raw[t])))*(1.0f-0.001f);
        sc[t] = rho*cosf(theta[t]);
        ss[t] = rho*sinf(theta[t]);
    }
    __syncthreads();
    float* Mo = g_M + m*65536;
    for (int idx = threadIdx.x; idx < 65536; idx += 256) {
        int r = idx>>8, c = idx&255;
        float val;
        if (r < 128) {
            if (c < 128) {
                int pr=r>>1, pc=c>>1;
                if (pr != pc) val = 0.0f;
                else val = ((r&1)==0) ? (((c&1)==0)?sc[pr]:-ss[pr])
                                      : (((c&1)==0)?ss[pr]:sc[pr]);
            } else val = K12[m*16384 + r*128 + (c-128)];
        } else {
            if (c < 128) val = K21[m*16384 + (r-128)*128 + c];
            else         val = K22[m*16384 + (r-128)*128 + (c-128)];
        }
        Mo[idx] = val;
    }
}

// -------- 1a) initial split images of M (transposed, k-paired, tiled) -----
__global__ __launch_bounds__(256) void init_split_kernel()
{
    __shared__ float T[64][65];
    int m = blockIdx.x >> 4, tile = blockIdx.x & 15;
    int kt = tile >> 2, nt = tile & 3;
    const float* M = g_M + m*65536;
    uint32_t* oh = g_simg[0][m][0];
    uint32_t* ol = g_simg[0][m][1];
    int tid = threadIdx.x;
#pragma unroll
    for (int it = 0; it < 16; it++) {
        int idx = tid + it*256;
        int row = idx>>6, col = idx&63;
        T[row][col] = M[(kt*64+row)*256 + nt*64 + col];
    }
    __syncthreads();
#pragma unroll
    for (int it = 0; it < 8; it++) {
        int idx = tid + it*256;          // 0..2047
        int n = idx>>5, j = idx&31;
        float v0 = T[2*j][n], v1 = T[2*j+1][n];
        int o = (nt*64+n)*128 + kt*32 + j;
        oh[o] = bfsplit_hi(v0, v1);
        ol[o] = bfsplit_lo(v0, v1);
    }
}

// -------- 1b) split W into bf16 hi/lo images --------
__global__ __launch_bounds__(256) void wsplit_kernel(
    const float* __restrict__ K12, const float* __restrict__ K22,
    const float* __restrict__ K21)
{
    int b = blockIdx.x;            // 0..23
    int mix = b>>3, m = b&7;
    const float* src = (mix==0) ? K12 : ((mix==1) ? K22 : K21);
    uint32_t* base = g_Wsw + ((size_t)mix*8 + m)*16384;
    for (int it = threadIdx.x; it < 8192; it += 256) {
        int n = it>>6, kpg = it&63;
        const float2 w = *(const float2*)(src + (size_t)m*16384 + n*128 + kpg*2);
        int kc = kpg>>4, kp = kpg&15;
        int off = kc*2048 + n*16 + kp;
        base[off]        = bfsplit_hi(w.x, w.y);
        base[8192 + off] = bfsplit_lo(w.x, w.y);
    }
}

// -------- 2) spec step: C = H^T H / fs_prev via mma.sync on split images --
#define SPEC_SMEM_BYTES 33536
__global__ void __launch_bounds__(256, 2) spec_kernel(int step)
{
    extern __shared__ uint32_t sm[];
    uint32_t* AsmH = sm;            // 128*20
    uint32_t* AsmL = sm + 2560;
    uint32_t* BsmH = sm + 5120;     // 64*20
    uint32_t* BsmL = sm + 6400;
    float*    Csm  = (float*)sm;    // union after MMA: 128 x 65 fp32
    __shared__ float red[256];

    int m = blockIdx.y, bx = blockIdx.x;
    int i0 = (bx&1)*128, j0 = (bx>>1)*64;
    int rb = step&1, wb = rb^1;
    const uint32_t* inH = g_simg[rb][m][0];
    const uint32_t* inL = g_simg[rb][m][1];
    uint32_t* outH = g_simg[wb][m][0];
    uint32_t* outL = g_simg[wb][m][1];

    int tid = threadIdx.x, wid = tid>>5, lane = tid&31;
    int r4 = lane>>2, l4 = lane&3;
    int wm = wid>>1, wn = wid&1;

    float inv = 1.0f;
    if (step > 0) {
        float s = 0.0f;
#pragma unroll
        for (int t=0;t<8;t++) s += g_fsp[step-1][m][t];
        inv = 1.0f/s;
    }

    float acc[2][4][4];
#pragma unroll
    for (int mt=0;mt<2;mt++)
#pragma unroll
        for (int nt=0;nt<4;nt++)
#pragma unroll
            for (int q=0;q<4;q++) acc[mt][nt][q]=0.0f;

    for (int kc = 0; kc < 8; kc++) {
        __syncthreads();
#pragma unroll
        for (int it = 0; it < 6; it++) {
            int q = tid + it*256;
            if (q < 1024) {
                int img = q>>9, c = (q>>2)&127, t4 = q&3;
                const uint4 v = *(const uint4*)((img ? inL : inH) + (i0+c)*128 + kc*16 + t4*4);
                *(uint4*)((img ? AsmL : AsmH) + c*20 + t4*4) = v;
            } else {
                int q2 = q - 1024;
                int img = q2>>8, c = (q2>>2)&63, t4 = q2&3;
                const uint4 v = *(const uint4*)((img ? inL : inH) + (j0+c)*128 + kc*16 + t4*4);
                *(uint4*)((img ? BsmL : BsmH) + c*20 + t4*4) = v;
            }
        }
        __syncthreads();

#pragma unroll
        for (int ks = 0; ks < 2; ks++) {
            uint32_t aH[2][4], aL[2][4], bH[4][2], bL[4][2];
            int kp = ks*8 + l4;
#pragma unroll
            for (int mt = 0; mt < 2; mt++) {
                int row = wm*32 + mt*16 + r4;
                aH[mt][0] = AsmH[row*20+kp];
                aH[mt][1] = AsmH[(row+8)*20+kp];
                aH[mt][2] = AsmH[row*20+kp+4];
                aH[mt][3] = AsmH[(row+8)*20+kp+4];
                aL[mt][0] = AsmL[row*20+kp];
                aL[mt][1] = AsmL[(row+8)*20+kp];
                aL[mt][2] = AsmL[row*20+kp+4];
                aL[mt][3] = AsmL[(row+8)*20+kp+4];
            }
#pragma unroll
            for (int nt = 0; nt < 4; nt++) {
                int n = wn*32 + nt*8 + r4;
                bH[nt][0] = BsmH[n*20+kp];
                bH[nt][1] = BsmH[n*20+kp+4];
                bL[nt][0] = BsmL[n*20+kp];
                bL[nt][1] = BsmL[n*20+kp+4];
            }
#pragma unroll
            for (int mt = 0; mt < 2; mt++)
#pragma unroll
                for (int nt = 0; nt < 4; nt++) {
                    mma_bf16(acc[mt][nt], aH[mt], bH[nt]);
                    mma_bf16(acc[mt][nt], aH[mt], bL[nt]);
                    mma_bf16(acc[mt][nt], aL[mt], bH[nt]);
                }
        }
    }

    __syncthreads();

    float lsum = 0.0f;
#pragma unroll
    for (int mt = 0; mt < 2; mt++)
#pragma unroll
        for (int nt = 0; nt < 4; nt++) {
            int row = wm*32 + mt*16 + r4;
            int col = wn*32 + nt*8 + l4*2;
            float v0 = acc[mt][nt][0]*inv, v1 = acc[mt][nt][1]*inv;
            float v2 = acc[mt][nt][2]*inv, v3 = acc[mt][nt][3]*inv;
            lsum += v0*v0 + v1*v1 + v2*v2 + v3*v3;
            Csm[row*65 + col] = v0;     Csm[row*65 + col + 1] = v1;
            Csm[(row+8)*65 + col] = v2; Csm[(row+8)*65 + col + 1] = v3;
        }
    __syncthreads();

#pragma unroll
    for (int it = 0; it < 16; it++) {
        int p = tid + it*256;
        int kp = p&63, nn = p>>6;
        float v0 = Csm[(2*kp)*65 + nn];
        float v1 = Csm[(2*kp+1)*65 + nn];
        int o = (j0+nn)*128 + (i0>>1) + kp;
        outH[o] = bfsplit_hi(v0, v1);
        outL[o] = bfsplit_lo(v0, v1);
    }

    red[tid]=lsum; __syncthreads();
    for (int s2=128;s2>0;s2>>=1) { if (tid<s2) red[tid]+=red[tid+s2]; __syncthreads(); }
    if (tid==0) g_fsp[step][m][bx]=red[0];
}

// -------- 3) finalize: sigma, scale, lambda --------
__global__ __launch_bounds__(64) void finalize_kernel(
    const float* __restrict__ rho_raw, const float* __restrict__ theta)
{
    __shared__ float s_sig[8];
    __shared__ float s_inv;
    int tid = threadIdx.x;
    if (tid < 8) {
        double lnl = 0.0, w = 1.0;
        for (int j=0;j<=NSQ;j++) {
            float fs = 0.0f;
            for (int t=0;t<8;t++) fs += g_fsp[j][tid][t];
            lnl += w*0.5*log((double)fs);
            w *= 0.5;
        }
        s_sig[tid] = (float)exp(0.5*lnl);
    }
    __syncthreads();
    if (tid == 0) {
        float s = 1.0f;
        for (int m=0;m<8;m++) s = fmaxf(s, s_sig[m]);
        s_inv = 1.0f/s;
        g_inv_s = s_inv;
    }
    __syncthreads();
    float rho = (1.0f/(1.0f+expf(-rho_raw[tid])))*(1.0f-0.001f);
    float mag = rho*s_inv;
    float th = theta[tid];
    float2 lam = make_float2(mag*cosf(th), mag*sinf(th));
    g_lam[tid] = lam;
    float2 q = lam;
    for (int i=0;i<7;i++) {
        float qr=q.x*q.x-q.y*q.y, qi=2.0f*q.x*q.y;
        q = make_float2(qr,qi);
    }
    g_lamL[tid] = q;
}

// -------- 4) gating softmax --------
__global__ __launch_bounds__(256) void gate_kernel(
    const float* __restrict__ u, const float* __restrict__ gw,
    const float* __restrict__ gb)
{
    __shared__ float sgw[1024];
    __shared__ float sgb[8];
    int tid = threadIdx.x;
    for (int i=tid;i<1024;i+=256) sgw[i]=gw[i];
    if (tid < 8) sgb[tid]=gb[tid];
    __syncthreads();
    int warp = tid>>5, lane = tid&31;
    int tok = blockIdx.x*8 + warp;
    float4 uv = ((const float4*)(u+(size_t)tok*128))[lane];
    float lg[8];
#pragma unroll
    for (int m=0;m<8;m++) {
        float4 w = ((const float4*)(sgw+m*128))[lane];
        float d = uv.x*w.x+uv.y*w.y+uv.z*w.z+uv.w*w.w;
#pragma unroll
        for (int s=16;s;s>>=1) d += __shfl_xor_sync(0xffffffffu,d,s);
        lg[m] = d + sgb[m];
    }
    float mx = lg[0];
#pragma unroll
    for (int m=1;m<8;m++) mx=fmaxf(mx,lg[m]);
    float e[8]; float sum=0.0f;
#pragma unroll
    for (int m=0;m<8;m++){ e[m]=expf(lg[m]-mx); sum+=e[m]; }
    float inv = 1.0f/sum;
#pragma unroll
    for (int m=0;m<8;m++)
        if (lane==m) g_pi[(size_t)tok*8+m] = e[m]*inv;
}

// -------- 5) mixture GEMM: cp.async double-buffered mma.sync + ldmatrix ---
// writes raw (unscaled) result to dst
#define MIX_DSMEM ((1024 + 4*2560 + 4*2560)*4)
__global__ void __launch_bounds__(256, 2) mix_mma_kernel(
    const float* __restrict__ A, const uint32_t* __restrict__ W,
    float* __restrict__ dst)
{
    extern __shared__ uint32_t dsm[];
    float*    pis  = (float*)dsm;           // 1024
    uint32_t* Abuf = dsm + 1024;            // [buf][img][2560]
    uint32_t* Wbuf = dsm + 1024 + 4*2560;   // [buf][img][2560]

    int tid = threadIdx.x, wid = tid>>5, lane = tid&31;
    int r4 = lane>>2, l4 = lane&3;
    int wm = wid>>2, wn = wid&3;
    int row0 = blockIdx.x*128;

    int sub = lane>>3, rr = lane&7;
    int aRowL = (sub&1)*8 + rr;
    int aColL = (sub>>1)*4;
    int bColL = (sub&1)*4;
    uint32_t smem_cvta = (uint32_t)__cvta_generic_to_shared(dsm);
    uint32_t aLaneOff = (uint32_t)((wm*64 + aRowL)*20 + aColL)*4;
    uint32_t bLaneOff = (uint32_t)((wn*32 + rr)*20 + bColL)*4;

    {
        const float4* gp = (const float4*)(g_pi + (size_t)row0*8);
        ((float4*)pis)[tid & 255] = gp[tid & 255];
    }
    __syncthreads();

    float acc[4][4][4];
#pragma unroll
    for (int mt=0;mt<4;mt++)
#pragma unroll
        for (int nt=0;nt<4;nt++)
#pragma unroll
            for (int q=0;q<4;q++) acc[mt][nt][q]=0.0f;

    // prologue: stage s=0
    {
        const uint32_t* wsrc = W;
#pragma unroll
        for (int it = 0; it < 2; it++) {
            int idx = tid + it*256;
            int n = idx>>2, q = idx&3;
            cp_async16(&Wbuf[n*20+q*4], wsrc + idx*4);
            cp_async16(&Wbuf[2560 + n*20+q*4], wsrc + 8192 + idx*4);
        }
        CP_COMMIT();
#pragma unroll
        for (int it = 0; it < 8; it++) {
            int idx = tid + it*256;
            int row = idx>>4, kp = idx&15;
            float2 a = *(const float2*)(A + (size_t)(row0+row)*128 + kp*2);
            float pim = pis[row*8];
            float v0 = a.x*pim, v1 = a.y*pim;
            Abuf[row*20+kp] = bfsplit_hi(v0, v1);
            Abuf[2560 + row*20+kp] = bfsplit_lo(v0, v1);
        }
        CP_WAIT0();
        __syncthreads();
    }

    for (int s = 0; s < 32; s++) {
        uint32_t acur = smem_cvta + (1024 + (s&1)*5120)*4;
        uint32_t wcur = smem_cvta + (1024 + 4*2560 + (s&1)*5120)*4;
        if (s+1 < 32) {
            int sn = s+1, mN = sn>>2, kcN = sn&3;
            uint32_t* Anxt = Abuf + ((s&1)^1)*5120;
            uint32_t* Wnxt = Wbuf + ((s&1)^1)*5120;
            const uint32_t* wsrc = W + (size_t)mN*16384 + kcN*2048;
#pragma unroll
            for (int it = 0; it < 2; it++) {
                int idx = tid + it*256;
                int n = idx>>2, q = idx&3;
                cp_async16(&Wnxt[n*20+q*4], wsrc + idx*4);
                cp_async16(&Wnxt[2560 + n*20+q*4], wsrc + 8192 + idx*4);
            }
            CP_COMMIT();
#pragma unroll
            for (int it = 0; it < 8; it++) {
                int idx = tid + it*256;
                int row = idx>>4, kp = idx&15;
                float2 a = *(const float2*)(A + (size_t)(row0+row)*128 + kcN*32 + kp*2);
                float pim = pis[row*8+mN];
                float v0 = a.x*pim, v1 = a.y*pim;
                Anxt[row*20+kp] = bfsplit_hi(v0, v1);
                Anxt[2560 + row*20+kp] = bfsplit_lo(v0, v1);
            }
        }

#pragma unroll
        for (int ks = 0; ks < 2; ks++) {
            uint32_t aH[4][4], aL[4][4], bH[4][2], bL[4][2];
            uint32_t kOff = (uint32_t)(ks*8)*4;
#pragma unroll
            for (int mt = 0; mt < 4; mt++) {
                uint32_t ao = acur + aLaneOff + (uint32_t)(mt*16*20)*4 + kOff;
                ldsm_x4(aH[mt][0], aH[mt][1], aH[mt][2], aH[mt][3], ao);
                ldsm_x4(aL[mt][0], aL[mt][1], aL[mt][2], aL[mt][3], ao + 2560*4);
            }
#pragma unroll
            for (int nt = 0; nt < 4; nt++) {
                uint32_t bo = wcur + bLaneOff + (uint32_t)(nt*8*20)*4 + kOff;
                ldsm_x2(bH[nt][0], bH[nt][1], bo);
                ldsm_x2(bL[nt][0], bL[nt][1], bo + 2560*4);
            }
#pragma unroll
            for (int mt = 0; mt < 4; mt++)
#pragma unroll
                for (int nt = 0; nt < 4; nt++) {
                    mma_bf16(acc[mt][nt], aH[mt], bH[nt]);
                    mma_bf16(acc[mt][nt], aH[mt], bL[nt]);
                    mma_bf16(acc[mt][nt], aL[mt], bH[nt]);
                }
        }
        CP_WAIT0();
        __syncthreads();
    }

#pragma unroll
    for (int mt = 0; mt < 4; mt++)
#pragma unroll
        for (int nt = 0; nt < 4; nt++) {
            int row = row0 + wm*64 + mt*16 + r4;
            int col = wn*32 + nt*8 + l4*2;
            *(float2*)(dst + (size_t)row*128 + col)
                = make_float2(acc[mt][nt][0], acc[mt][nt][1]);
            *(float2*)(dst + (size_t)(row+8)*128 + col)
                = make_float2(acc[mt][nt][2], acc[mt][nt][3]);
        }
}

// -------- 5b) combine: out = (y22_raw + y21_raw) * inv_s --------
__global__ __launch_bounds__(256) void combine_kernel(float* __restrict__ out)
{
    size_t i = (size_t)blockIdx.x*256 + threadIdx.x;
    float s = g_inv_s;
    float4 a = ((float4*)out)[i];
    float4 b = ((const float4*)g_y21)[i];
    a.x = (a.x+b.x)*s; a.y = (a.y+b.y)*s;
    a.z = (a.z+b.z)*s; a.w = (a.w+b.w)*s;
    ((float4*)out)[i] = a;
}

// -------- 6) chunked complex scan (applies inv_s to v on the fly) --------
__global__ __launch_bounds__(64) void scanA_kernel()
{
    int b = blockIdx.x>>6, c = blockIdx.x&63, p = threadIdx.x;
    float2 lam = g_lam[p];
    float sc = g_inv_s;
    const float2* vp = (const float2*)g_v + (size_t)(b*TLEN+c*128)*64 + p;
    float2 w = make_float2(0.0f,0.0f);
    for (int t=0;t<128;t++) {
        float2 x = vp[(size_t)t*64];
        x.x *= sc; x.y *= sc;
        float wr = fmaf(lam.x,w.x,fmaf(-lam.y,w.y,x.x));
        float wi = fmaf(lam.x,w.y,fmaf(lam.y,w.x,x.y));
        w = make_float2(wr,wi);
    }
    g_carry[(b*64+c)*64+p] = w;
}

__global__ __launch_bounds__(256) void scanB_kernel()
{
    int tid = threadIdx.x;
    int b = tid>>6, p = tid&63;
    float2 q = g_lamL[p];
    float2 w = make_float2(0.0f,0.0f);
    for (int c=0;c<64;c++) {
        g_Cin[(b*64+c)*64+p] = w;
        float2 s = g_carry[(b*64+c)*64+p];
        float wr = fmaf(q.x,w.x,fmaf(-q.y,w.y,s.x));
        float wi = fmaf(q.x,w.y,fmaf(q.y,w.x,s.y));
        w = make_float2(wr,wi);
    }
}

__global__ __launch_bounds__(64) void scanC_kernel(float* __restrict__ zout)
{
    int b = blockIdx.x>>6, c = blockIdx.x&63, p = threadIdx.x;
    float2 lam = g_lam[p];
    float sc = g_inv_s;
    float2 w = g_Cin[(b*64+c)*64+p];
    const float2* vp = (const float2*)g_v + (size_t)(b*TLEN+c*128)*64 + p;
    float2* zp = (float2*)zout + (size_t)(b*TLEN+c*128)*64 + p;
    for (int t=0;t<128;t++) {
        float2 x = vp[(size_t)t*64];
        x.x *= sc; x.y *= sc;
        zp[(size_t)t*64] = w;
        float wr = fmaf(lam.x,w.x,fmaf(-lam.y,w.y,x.x));
        float wi = fmaf(lam.x,w.y,fmaf(lam.y,w.x,x.y));
        w = make_float2(wr,wi);
    }
}

extern "C" void kernel_launch(void* const* d_in, const int* in_sizes, int n_in,
                              void* d_out, int out_size)
{
    const float* u   = (const float*)d_in[0];
    const float* rho = (const float*)d_in[1];
    const float* th  = (const float*)d_in[2];
    const float* K12 = (const float*)d_in[3];
    const float* K21 = (const float*)d_in[4];
    const float* K22 = (const float*)d_in[5];
    const float* gw  = (const float*)d_in[6];
    const float* gb  = (const float*)d_in[7];
    float* out = (float*)d_out;

    float* zdst;
    if (out_size >= 2*4194304) {
        zdst = out + (size_t)4194304;
    } else {
        void* p; cudaGetSymbolAddress(&p, g_zscr);
        zdst = (float*)p;
    }
    void* pW; cudaGetSymbolAddress(&pW, g_Wsw);
    void* pV; cudaGetSymbolAddress(&pV, g_v);
    void* pY; cudaGetSymbolAddress(&pY, g_y21);
    const uint32_t* Wbase = (const uint32_t*)pW;
    float* vptr = (float*)pV;
    float* y21ptr = (float*)pY;

    static cudaStream_t s1 = nullptr, s2 = nullptr;
    static cudaEvent_t e0 = nullptr, e1 = nullptr, e2 = nullptr, e3 = nullptr;
    if (s1 == nullptr) {
        int plo, phi;
        cudaDeviceGetStreamPriorityRange(&plo, &phi);
        cudaStreamCreateWithPriority(&s1, cudaStreamNonBlocking, plo); // side: low
        cudaStreamCreateWithPriority(&s2, cudaStreamNonBlocking, phi); // spec: high
        cudaEventCreateWithFlags(&e0, cudaEventDisableTiming);
        cudaEventCreateWithFlags(&e1, cudaEventDisableTiming);
        cudaEventCreateWithFlags(&e2, cudaEventDisableTiming);
        cudaEventCreateWithFlags(&e3, cudaEventDisableTiming);
        cudaFuncSetAttribute(mix_mma_kernel,
            cudaFuncAttributeMaxDynamicSharedMemorySize, MIX_DSMEM);
    }

    cudaEventRecord(e0, 0);
    cudaStreamWaitEvent(s1, e0, 0);
    cudaStreamWaitEvent(s2, e0, 0);

    // side stream (low prio): s-independent token work
    wsplit_kernel<<<24,256,0,s1>>>(K12, K22, K21);
    gate_kernel<<<4096,256,0,s1>>>(u, gw, gb);
    mix_mma_kernel<<<256,256,MIX_DSMEM,s1>>>(u, Wbase + 0, vptr);       // v_raw
    cudaEventRecord(e1, s1);                                            // scans gate here
    mix_mma_kernel<<<256,256,MIX_DSMEM,s1>>>(u, Wbase + 131072, out);   // y22_raw
    cudaEventRecord(e3, s1);                                            // combine gates here

    // spec stream (high prio): spectral chain
    prep_kernel<<<8,256,0,s2>>>(rho, th, K12, K21, K22);
    init_split_kernel<<<128,256,0,s2>>>();
    for (int s=0;s<=NSQ;s++) spec_kernel<<<dim3(8,8),256,SPEC_SMEM_BYTES,s2>>>(s);
    finalize_kernel<<<1,64,0,s2>>>(rho, th);
    cudaEventRecord(e2, s2);

    // default stream: scans need only {mix1, spec}; mix3 is decoupled from mix2
    cudaStreamWaitEvent(0, e1, 0);
    cudaStreamWaitEvent(0, e2, 0);
    scanA_kernel<<<256,64>>>();
    scanB_kernel<<<1,256>>>();
    scanC_kernel<<<256,64>>>(zdst);
    mix_mma_kernel<<<256,256,MIX_DSMEM>>>(zdst, Wbase + 262144, y21ptr); // y21_raw
    cudaStreamWaitEvent(0, e3, 0);
    combine_kernel<<<4096,256>>>(out);                                   // (y22+y21)*inv_s
}

// round 15
// speedup vs baseline: 1.5400x; 1.5400x over previous
#include <cuda_runtime.h>
#include <cuda_bf16.h>
#include <math.h>
#include <stdint.h>

#define NSQ 12
#define NTOK 32768
#define TLEN 8192

__device__ float  g_M[8*65536];
__device__ float  g_fsp[NSQ+1][8][8];
__device__ float  g_inv_s;
__device__ float2 g_lam[64];
__device__ float2 g_lamL[64];
__device__ float  g_pi[NTOK*8];
__device__ float  g_v[(size_t)NTOK*128];
__device__ float  g_zscr[(size_t)NTOK*128];
__device__ float2 g_carry[4*64*64];
__device__ float2 g_Cin[4*64*64];
// spectral split images: [buf 2][m 8][img 2][n 256][kp 128] u32 (bf16x2, k-pairs)
__device__ uint32_t g_simg[2][8][2][32768];
// W split images: [mix 3][m 8][img 2][kc 4][n 128][kp 16] u32 (bf16x2)
__device__ uint32_t g_Wsw[3*8*2*4*2048];

__device__ __forceinline__ uint32_t bfsplit_hi(float a, float b) {
    __nv_bfloat16 h0 = __float2bfloat16(a), h1 = __float2bfloat16(b);
    return (uint32_t)__bfloat16_as_ushort(h0) | ((uint32_t)__bfloat16_as_ushort(h1) << 16);
}
__device__ __forceinline__ uint32_t bfsplit_lo(float a, float b) {
    __nv_bfloat16 h0 = __float2bfloat16(a), h1 = __float2bfloat16(b);
    float r0 = a - __bfloat162float(h0), r1 = b - __bfloat162float(h1);
    __nv_bfloat16 l0 = __float2bfloat16(r0), l1 = __float2bfloat16(r1);
    return (uint32_t)__bfloat16_as_ushort(l0) | ((uint32_t)__bfloat16_as_ushort(l1) << 16);
}
__device__ __forceinline__ void mma_bf16(float* c, const uint32_t* a, const uint32_t* b) {
    asm volatile(
        "mma.sync.aligned.m16n8k16.row.col.f32.bf16.bf16.f32 "
        "{%0,%1,%2,%3},{%4,%5,%6,%7},{%8,%9},{%0,%1,%2,%3};"
        : "+f"(c[0]), "+f"(c[1]), "+f"(c[2]), "+f"(c[3])
        : "r"(a[0]), "r"(a[1]), "r"(a[2]), "r"(a[3]), "r"(b[0]), "r"(b[1]));
}
__device__ __forceinline__ void cp_async16(void* smem_dst, const void* gsrc) {
    unsigned sa = (unsigned)__cvta_generic_to_shared(smem_dst);
    asm volatile("cp.async.cg.shared.global [%0], [%1], 16;" :: "r"(sa), "l"(gsrc) : "memory");
}
#define CP_COMMIT() asm volatile("cp.async.commit_group;" ::: "memory")
#define CP_WAIT0()  asm volatile("cp.async.wait_group 0;" ::: "memory")
__device__ __forceinline__ void ldsm_x4(uint32_t& r0, uint32_t& r1, uint32_t& r2,
                                        uint32_t& r3, uint32_t addr) {
    asm volatile("ldmatrix.sync.aligned.m8n8.x4.shared.b16 {%0,%1,%2,%3},[%4];"
        : "=r"(r0), "=r"(r1), "=r"(r2), "=r"(r3) : "r"(addr));
}
__device__ __forceinline__ void ldsm_x2(uint32_t& r0, uint32_t& r1, uint32_t addr) {
    asm volatile("ldmatrix.sync.aligned.m8n8.x2.shared.b16 {%0,%1},[%2];"
        : "=r"(r0), "=r"(r1) : "r"(addr));
}

// -------- 1) assemble K_raw per expert (256x256) --------
__global__ __launch_bounds__(256) void prep_kernel(
    const float* __restrict__ rho_raw, const float* __restrict__ theta,
    const float* __restrict__ K12, const float* __restrict__ K21,
    const float* __restrict__ K22)
{
    __shared__ float sc[64], ss[64];
    int m = blockIdx.x;
    if (threadIdx.x < 64) {
        int t = threadIdx.x;
        float rho = (1.0f/(1.0f+expf(-rho_raw[t])))*(1.0f-0.001f);
        sc[t] = rho*cosf(theta[t]);
        ss[t] = rho*sinf(theta[t]);
    }
    __syncthreads();
    float* Mo = g_M + m*65536;
    for (int idx = threadIdx.x; idx < 65536; idx += 256) {
        int r = idx>>8, c = idx&255;
        float val;
        if (r < 128) {
            if (c < 128) {
                int pr=r>>1, pc=c>>1;
                if (pr != pc) val = 0.0f;
                else val = ((r&1)==0) ? (((c&1)==0)?sc[pr]:-ss[pr])
                                      : (((c&1)==0)?ss[pr]:sc[pr]);
            } else val = K12[m*16384 + r*128 + (c-128)];
        } else {
            if (c < 128) val = K21[m*16384 + (r-128)*128 + c];
            else         val = K22[m*16384 + (r-128)*128 + (c-128)];
        }
        Mo[idx] = val;
    }
}

// -------- 1a) initial split images of M (transposed, k-paired, tiled) -----
__global__ __launch_bounds__(256) void init_split_kernel()
{
    __shared__ float T[64][65];
    int m = blockIdx.x >> 4, tile = blockIdx.x & 15;
    int kt = tile >> 2, nt = tile & 3;
    const float* M = g_M + m*65536;
    uint32_t* oh = g_simg[0][m][0];
    uint32_t* ol = g_simg[0][m][1];
    int tid = threadIdx.x;
#pragma unroll
    for (int it = 0; it < 16; it++) {
        int idx = tid + it*256;
        int row = idx>>6, col = idx&63;
        T[row][col] = M[(kt*64+row)*256 + nt*64 + col];
    }
    __syncthreads();
#pragma unroll
    for (int it = 0; it < 8; it++) {
        int idx = tid + it*256;          // 0..2047
        int n = idx>>5, j = idx&31;
        float v0 = T[2*j][n], v1 = T[2*j+1][n];
        int o = (nt*64+n)*128 + kt*32 + j;
        oh[o] = bfsplit_hi(v0, v1);
        ol[o] = bfsplit_lo(v0, v1);
    }
}

// -------- 1b) split W into bf16 hi/lo images --------
__global__ __launch_bounds__(256) void wsplit_kernel(
    const float* __restrict__ K12, const float* __restrict__ K22,
    const float* __restrict__ K21)
{
    int b = blockIdx.x;            // 0..23
    int mix = b>>3, m = b&7;
    const float* src = (mix==0) ? K12 : ((mix==1) ? K22 : K21);
    uint32_t* base = g_Wsw + ((size_t)mix*8 + m)*16384;
    for (int it = threadIdx.x; it < 8192; it += 256) {
        int n = it>>6, kpg = it&63;
        const float2 w = *(const float2*)(src + (size_t)m*16384 + n*128 + kpg*2);
        int kc = kpg>>4, kp = kpg&15;
        int off = kc*2048 + n*16 + kp;
        base[off]        = bfsplit_hi(w.x, w.y);
        base[8192 + off] = bfsplit_lo(w.x, w.y);
    }
}

// -------- 2) spec step: C = H^T H / fs_prev via mma.sync on split images --
#define SPEC_SMEM_BYTES 33536
__global__ void __launch_bounds__(256, 2) spec_kernel(int step)
{
    extern __shared__ uint32_t sm[];
    uint32_t* AsmH = sm;            // 128*20
    uint32_t* AsmL = sm + 2560;
    uint32_t* BsmH = sm + 5120;     // 64*20
    uint32_t* BsmL = sm + 6400;
    float*    Csm  = (float*)sm;    // union after MMA: 128 x 65 fp32
    __shared__ float red[256];

    int m = blockIdx.y, bx = blockIdx.x;
    int i0 = (bx&1)*128, j0 = (bx>>1)*64;
    int rb = step&1, wb = rb^1;
    const uint32_t* inH = g_simg[rb][m][0];
    const uint32_t* inL = g_simg[rb][m][1];
    uint32_t* outH = g_simg[wb][m][0];
    uint32_t* outL = g_simg[wb][m][1];

    int tid = threadIdx.x, wid = tid>>5, lane = tid&31;
    int r4 = lane>>2, l4 = lane&3;
    int wm = wid>>1, wn = wid&1;

    float inv = 1.0f;
    if (step > 0) {
        float s = 0.0f;
#pragma unroll
        for (int t=0;t<8;t++) s += g_fsp[step-1][m][t];
        inv = 1.0f/s;
    }

    float acc[2][4][4];
#pragma unroll
    for (int mt=0;mt<2;mt++)
#pragma unroll
        for (int nt=0;nt<4;nt++)
#pragma unroll
            for (int q=0;q<4;q++) acc[mt][nt][q]=0.0f;

    for (int kc = 0; kc < 8; kc++) {
        __syncthreads();
#pragma unroll
        for (int it = 0; it < 6; it++) {
            int q = tid + it*256;
            if (q < 1024) {
                int img = q>>9, c = (q>>2)&127, t4 = q&3;
                const uint4 v = *(const uint4*)((img ? inL : inH) + (i0+c)*128 + kc*16 + t4*4);
                *(uint4*)((img ? AsmL : AsmH) + c*20 + t4*4) = v;
            } else {
                int q2 = q - 1024;
                int img = q2>>8, c = (q2>>2)&63, t4 = q2&3;
                const uint4 v = *(const uint4*)((img ? inL : inH) + (j0+c)*128 + kc*16 + t4*4);
                *(uint4*)((img ? BsmL : BsmH) + c*20 + t4*4) = v;
            }
        }
        __syncthreads();

#pragma unroll
        for (int ks = 0; ks < 2; ks++) {
            uint32_t aH[2][4], aL[2][4], bH[4][2], bL[4][2];
            int kp = ks*8 + l4;
#pragma unroll
            for (int mt = 0; mt < 2; mt++) {
                int row = wm*32 + mt*16 + r4;
                aH[mt][0] = AsmH[row*20+kp];
                aH[mt][1] = AsmH[(row+8)*20+kp];
                aH[mt][2] = AsmH[row*20+kp+4];
                aH[mt][3] = AsmH[(row+8)*20+kp+4];
                aL[mt][0] = AsmL[row*20+kp];
                aL[mt][1] = AsmL[(row+8)*20+kp];
                aL[mt][2] = AsmL[row*20+kp+4];
                aL[mt][3] = AsmL[(row+8)*20+kp+4];
            }
#pragma unroll
            for (int nt = 0; nt < 4; nt++) {
                int n = wn*32 + nt*8 + r4;
                bH[nt][0] = BsmH[n*20+kp];
                bH[nt][1] = BsmH[n*20+kp+4];
                bL[nt][0] = BsmL[n*20+kp];
                bL[nt][1] = BsmL[n*20+kp+4];
            }
#pragma unroll
            for (int mt = 0; mt < 2; mt++)
#pragma unroll
                for (int nt = 0; nt < 4; nt++) {
                    mma_bf16(acc[mt][nt], aH[mt], bH[nt]);
                    mma_bf16(acc[mt][nt], aH[mt], bL[nt]);
                    mma_bf16(acc[mt][nt], aL[mt], bH[nt]);
                }
        }
    }

    __syncthreads();

    float lsum = 0.0f;
#pragma unroll
    for (int mt = 0; mt < 2; mt++)
#pragma unroll
        for (int nt = 0; nt < 4; nt++) {
            int row = wm*32 + mt*16 + r4;
            int col = wn*32 + nt*8 + l4*2;
            float v0 = acc[mt][nt][0]*inv, v1 = acc[mt][nt][1]*inv;
            float v2 = acc[mt][nt][2]*inv, v3 = acc[mt][nt][3]*inv;
            lsum += v0*v0 + v1*v1 + v2*v2 + v3*v3;
            Csm[row*65 + col] = v0;     Csm[row*65 + col + 1] = v1;
            Csm[(row+8)*65 + col] = v2; Csm[(row+8)*65 + col + 1] = v3;
        }
    __syncthreads();

#pragma unroll
    for (int it = 0; it < 16; it++) {
        int p = tid + it*256;
        int kp = p&63, nn = p>>6;
        float v0 = Csm[(2*kp)*65 + nn];
        float v1 = Csm[(2*kp+1)*65 + nn];
        int o = (j0+nn)*128 + (i0>>1) + kp;
        outH[o] = bfsplit_hi(v0, v1);
        outL[o] = bfsplit_lo(v0, v1);
    }

    red[tid]=lsum; __syncthreads();
    for (int s2=128;s2>0;s2>>=1) { if (tid<s2) red[tid]+=red[tid+s2]; __syncthreads(); }
    if (tid==0) g_fsp[step][m][bx]=red[0];
}

// -------- 3) finalize: sigma, scale, lambda --------
__global__ __launch_bounds__(64) void finalize_kernel(
    const float* __restrict__ rho_raw, const float* __restrict__ theta)
{
    __shared__ float s_sig[8];
    __shared__ float s_inv;
    int tid = threadIdx.x;
    if (tid < 8) {
        double lnl = 0.0, w = 1.0;
        for (int j=0;j<=NSQ;j++) {
            float fs = 0.0f;
            for (int t=0;t<8;t++) fs += g_fsp[j][tid][t];
            lnl += w*0.5*log((double)fs);
            w *= 0.5;
        }
        s_sig[tid] = (float)exp(0.5*lnl);
    }
    __syncthreads();
    if (tid == 0) {
        float s = 1.0f;
        for (int m=0;m<8;m++) s = fmaxf(s, s_sig[m]);
        s_inv = 1.0f/s;
        g_inv_s = s_inv;
    }
    __syncthreads();
    float rho = (1.0f/(1.0f+expf(-rho_raw[tid])))*(1.0f-0.001f);
    float mag = rho*s_inv;
    float th = theta[tid];
    float2 lam = make_float2(mag*cosf(th), mag*sinf(th));
    g_lam[tid] = lam;
    float2 q = lam;
    for (int i=0;i<7;i++) {
        float qr=q.x*q.x-q.y*q.y, qi=2.0f*q.x*q.y;
        q = make_float2(qr,qi);
    }
    g_lamL[tid] = q;
}

// -------- 4) gating softmax --------
__global__ __launch_bounds__(256) void gate_kernel(
    const float* __restrict__ u, const float* __restrict__ gw,
    const float* __restrict__ gb)
{
    __shared__ float sgw[1024];
    __shared__ float sgb[8];
    int tid = threadIdx.x;
    for (int i=tid;i<1024;i+=256) sgw[i]=gw[i];
    if (tid < 8) sgb[tid]=gb[tid];
    __syncthreads();
    int warp = tid>>5, lane = tid&31;
    int tok = blockIdx.x*8 + warp;
    float4 uv = ((const float4*)(u+(size_t)tok*128))[lane];
    float lg[8];
#pragma unroll
    for (int m=0;m<8;m++) {
        float4 w = ((const float4*)(sgw+m*128))[lane];
        float d = uv.x*w.x+uv.y*w.y+uv.z*w.z+uv.w*w.w;
#pragma unroll
        for (int s=16;s;s>>=1) d += __shfl_xor_sync(0xffffffffu,d,s);
        lg[m] = d + sgb[m];
    }
    float mx = lg[0];
#pragma unroll
    for (int m=1;m<8;m++) mx=fmaxf(mx,lg[m]);
    float e[8]; float sum=0.0f;
#pragma unroll
    for (int m=0;m<8;m++){ e[m]=expf(lg[m]-mx); sum+=e[m]; }
    float inv = 1.0f/sum;
#pragma unroll
    for (int m=0;m<8;m++)
        if (lane==m) g_pi[(size_t)tok*8+m] = e[m]*inv;
}

// -------- 5) mixture GEMM: cp.async double-buffered mma.sync + ldmatrix ---
// mode 0: dst = raw result ; mode 2: dst = (dst + raw)*g_inv_s
#define MIX_DSMEM ((1024 + 4*2560 + 4*2560)*4)
__global__ void __launch_bounds__(256, 2) mix_mma_kernel(
    const float* __restrict__ A, const uint32_t* __restrict__ W,
    float* __restrict__ dst, int mode)
{
    extern __shared__ uint32_t dsm[];
    float*    pis  = (float*)dsm;           // 1024
    uint32_t* Abuf = dsm + 1024;            // [buf][img][2560]
    uint32_t* Wbuf = dsm + 1024 + 4*2560;   // [buf][img][2560]

    int tid = threadIdx.x, wid = tid>>5, lane = tid&31;
    int r4 = lane>>2, l4 = lane&3;
    int wm = wid>>2, wn = wid&3;
    int row0 = blockIdx.x*128;

    int sub = lane>>3, rr = lane&7;
    int aRowL = (sub&1)*8 + rr;
    int aColL = (sub>>1)*4;
    int bColL = (sub&1)*4;
    uint32_t smem_cvta = (uint32_t)__cvta_generic_to_shared(dsm);
    uint32_t aLaneOff = (uint32_t)((wm*64 + aRowL)*20 + aColL)*4;
    uint32_t bLaneOff = (uint32_t)((wn*32 + rr)*20 + bColL)*4;

    {
        const float4* gp = (const float4*)(g_pi + (size_t)row0*8);
        ((float4*)pis)[tid & 255] = gp[tid & 255];
    }
    __syncthreads();

    float acc[4][4][4];
#pragma unroll
    for (int mt=0;mt<4;mt++)
#pragma unroll
        for (int nt=0;nt<4;nt++)
#pragma unroll
            for (int q=0;q<4;q++) acc[mt][nt][q]=0.0f;

    // prologue: stage s=0  (512 x 16B per image)
    {
        const uint32_t* wsrc = W;
#pragma unroll
        for (int it = 0; it < 2; it++) {
            int idx = tid + it*256;
            int n = idx>>2, q = idx&3;
            cp_async16(&Wbuf[n*20+q*4], wsrc + idx*4);
            cp_async16(&Wbuf[2560 + n*20+q*4], wsrc + 8192 + idx*4);
        }
        CP_COMMIT();
#pragma unroll
        for (int it = 0; it < 8; it++) {
            int idx = tid + it*256;
            int row = idx>>4, kp = idx&15;
            float2 a = *(const float2*)(A + (size_t)(row0+row)*128 + kp*2);
            float pim = pis[row*8];
            float v0 = a.x*pim, v1 = a.y*pim;
            Abuf[row*20+kp] = bfsplit_hi(v0, v1);
            Abuf[2560 + row*20+kp] = bfsplit_lo(v0, v1);
        }
        CP_WAIT0();
        __syncthreads();
    }

    for (int s = 0; s < 32; s++) {
        uint32_t acur = smem_cvta + (1024 + (s&1)*5120)*4;
        uint32_t wcur = smem_cvta + (1024 + 4*2560 + (s&1)*5120)*4;
        if (s+1 < 32) {
            int sn = s+1, mN = sn>>2, kcN = sn&3;
            uint32_t* Anxt = Abuf + ((s&1)^1)*5120;
            uint32_t* Wnxt = Wbuf + ((s&1)^1)*5120;
            const uint32_t* wsrc = W + (size_t)mN*16384 + kcN*2048;
#pragma unroll
            for (int it = 0; it < 2; it++) {
                int idx = tid + it*256;
                int n = idx>>2, q = idx&3;
                cp_async16(&Wnxt[n*20+q*4], wsrc + idx*4);
                cp_async16(&Wnxt[2560 + n*20+q*4], wsrc + 8192 + idx*4);
            }
            CP_COMMIT();
#pragma unroll
            for (int it = 0; it < 8; it++) {
                int idx = tid + it*256;
                int row = idx>>4, kp = idx&15;
                float2 a = *(const float2*)(A + (size_t)(row0+row)*128 + kcN*32 + kp*2);
                float pim = pis[row*8+mN];
                float v0 = a.x*pim, v1 = a.y*pim;
                Anxt[row*20+kp] = bfsplit_hi(v0, v1);
                Anxt[2560 + row*20+kp] = bfsplit_lo(v0, v1);
            }
        }

#pragma unroll
        for (int ks = 0; ks < 2; ks++) {
            uint32_t aH[4][4], aL[4][4], bH[4][2], bL[4][2];
            uint32_t kOff = (uint32_t)(ks*8)*4;
#pragma unroll
            for (int mt = 0; mt < 4; mt++) {
                uint32_t ao = acur + aLaneOff + (uint32_t)(mt*16*20)*4 + kOff;
                ldsm_x4(aH[mt][0], aH[mt][1], aH[mt][2], aH[mt][3], ao);
                ldsm_x4(aL[mt][0], aL[mt][1], aL[mt][2], aL[mt][3], ao + 2560*4);
            }
#pragma unroll
            for (int nt = 0; nt < 4; nt++) {
                uint32_t bo = wcur + bLaneOff + (uint32_t)(nt*8*20)*4 + kOff;
                ldsm_x2(bH[nt][0], bH[nt][1], bo);
                ldsm_x2(bL[nt][0], bL[nt][1], bo + 2560*4);
            }
#pragma unroll
            for (int mt = 0; mt < 4; mt++)
#pragma unroll
                for (int nt = 0; nt < 4; nt++) {
                    mma_bf16(acc[mt][nt], aH[mt], bH[nt]);
                    mma_bf16(acc[mt][nt], aH[mt], bL[nt]);
                    mma_bf16(acc[mt][nt], aL[mt], bH[nt]);
                }
        }
        CP_WAIT0();
        __syncthreads();
    }

    float sc = g_inv_s;
#pragma unroll
    for (int mt = 0; mt < 4; mt++)
#pragma unroll
        for (int nt = 0; nt < 4; nt++) {
            int row = row0 + wm*64 + mt*16 + r4;
            int col = wn*32 + nt*8 + l4*2;
            float2* p0 = (float2*)(dst + (size_t)row*128 + col);
            float2* p1 = (float2*)(dst + (size_t)(row+8)*128 + col);
            float2 o0, o1;
            if (mode == 2) {
                float2 e0 = *p0, e1 = *p1;
                o0 = make_float2((e0.x+acc[mt][nt][0])*sc, (e0.y+acc[mt][nt][1])*sc);
                o1 = make_float2((e1.x+acc[mt][nt][2])*sc, (e1.y+acc[mt][nt][3])*sc);
            } else {
                o0 = make_float2(acc[mt][nt][0], acc[mt][nt][1]);
                o1 = make_float2(acc[mt][nt][2], acc[mt][nt][3]);
            }
            *p0 = o0; *p1 = o1;
        }
}

// -------- 6) chunked complex scan (applies inv_s to v on the fly) --------
__global__ __launch_bounds__(64) void scanA_kernel()
{
    int b = blockIdx.x>>6, c = blockIdx.x&63, p = threadIdx.x;
    float2 lam = g_lam[p];
    float sc = g_inv_s;
    const float2* vp = (const float2*)g_v + (size_t)(b*TLEN+c*128)*64 + p;
    float2 w = make_float2(0.0f,0.0f);
    for (int t=0;t<128;t++) {
        float2 x = vp[(size_t)t*64];
        x.x *= sc; x.y *= sc;
        float wr = fmaf(lam.x,w.x,fmaf(-lam.y,w.y,x.x));
        float wi = fmaf(lam.x,w.y,fmaf(lam.y,w.x,x.y));
        w = make_float2(wr,wi);
    }
    g_carry[(b*64+c)*64+p] = w;
}

// group-prefetched serial carry combine (identical math order to before)
__global__ __launch_bounds__(256) void scanB_kernel()
{
    int tid = threadIdx.x;
    int b = tid>>6, p = tid&63;
    float2 q = g_lamL[p];
    float2 w = make_float2(0.0f,0.0f);
    float2 buf[8], nbuf[8];
#pragma unroll
    for (int j=0;j<8;j++) buf[j] = g_carry[(b*64 + j)*64 + p];
    for (int g=0; g<8; g++) {
        if (g < 7) {
#pragma unroll
            for (int j=0;j<8;j++) nbuf[j] = g_carry[(b*64 + (g+1)*8 + j)*64 + p];
        }
#pragma unroll
        for (int j=0;j<8;j++) {
            int c = g*8 + j;
            g_Cin[(b*64+c)*64+p] = w;
            float2 s = buf[j];
            float wr = fmaf(q.x,w.x,fmaf(-q.y,w.y,s.x));
            float wi = fmaf(q.x,w.y,fmaf(q.y,w.x,s.y));
            w = make_float2(wr,wi);
        }
#pragma unroll
        for (int j=0;j<8;j++) buf[j] = nbuf[j];
    }
}

__global__ __launch_bounds__(64) void scanC_kernel(float* __restrict__ zout)
{
    int b = blockIdx.x>>6, c = blockIdx.x&63, p = threadIdx.x;
    float2 lam = g_lam[p];
    float sc = g_inv_s;
    float2 w = g_Cin[(b*64+c)*64+p];
    const float2* vp = (const float2*)g_v + (size_t)(b*TLEN+c*128)*64 + p;
    float2* zp = (float2*)zout + (size_t)(b*TLEN+c*128)*64 + p;
    for (int t=0;t<128;t++) {
        float2 x = vp[(size_t)t*64];
        x.x *= sc; x.y *= sc;
        zp[(size_t)t*64] = w;
        float wr = fmaf(lam.x,w.x,fmaf(-lam.y,w.y,x.x));
        float wi = fmaf(lam.x,w.y,fmaf(lam.y,w.x,x.y));
        w = make_float2(wr,wi);
    }
}

extern "C" void kernel_launch(void* const* d_in, const int* in_sizes, int n_in,
                              void* d_out, int out_size)
{
    const float* u   = (const float*)d_in[0];
    const float* rho = (const float*)d_in[1];
    const float* th  = (const float*)d_in[2];
    const float* K12 = (const float*)d_in[3];
    const float* K21 = (const float*)d_in[4];
    const float* K22 = (const float*)d_in[5];
    const float* gw  = (const float*)d_in[6];
    const float* gb  = (const float*)d_in[7];
    float* out = (float*)d_out;

    float* zdst;
    if (out_size >= 2*4194304) {
        zdst = out + (size_t)4194304;
    } else {
        void* p; cudaGetSymbolAddress(&p, g_zscr);
        zdst = (float*)p;
    }
    void* pW; cudaGetSymbolAddress(&pW, g_Wsw);
    void* pV; cudaGetSymbolAddress(&pV, g_v);
    const uint32_t* Wbase = (const uint32_t*)pW;
    float* vptr = (float*)pV;

    static cudaStream_t s1 = nullptr, s2 = nullptr;
    static cudaEvent_t e0 = nullptr, e1 = nullptr, e2 = nullptr;
    if (s1 == nullptr) {
        int plo, phi;
        cudaDeviceGetStreamPriorityRange(&plo, &phi);
        cudaStreamCreateWithPriority(&s1, cudaStreamNonBlocking, plo); // side: low
        cudaStreamCreateWithPriority(&s2, cudaStreamNonBlocking, phi); // spec: high
        cudaEventCreateWithFlags(&e0, cudaEventDisableTiming);
        cudaEventCreateWithFlags(&e1, cudaEventDisableTiming);
        cudaEventCreateWithFlags(&e2, cudaEventDisableTiming);
        cudaFuncSetAttribute(mix_mma_kernel,
            cudaFuncAttributeMaxDynamicSharedMemorySize, MIX_DSMEM);
    }

    cudaEventRecord(e0, 0);
    cudaStreamWaitEvent(s1, e0, 0);
    cudaStreamWaitEvent(s2, e0, 0);

    // side stream (low prio): s-independent token work (mixes strictly serialized)
    wsplit_kernel<<<24,256,0,s1>>>(K12, K22, K21);
    gate_kernel<<<4096,256,0,s1>>>(u, gw, gb);
    mix_mma_kernel<<<256,256,MIX_DSMEM,s1>>>(u, Wbase + 0,      vptr, 0); // v_raw
    mix_mma_kernel<<<256,256,MIX_DSMEM,s1>>>(u, Wbase + 131072, out,  0); // y22_raw
    cudaEventRecord(e1, s1);

    // spec stream (high prio): spectral chain
    prep_kernel<<<8,256,0,s2>>>(rho, th, K12, K21, K22);
    init_split_kernel<<<128,256,0,s2>>>();
    for (int s=0;s<=NSQ;s++) spec_kernel<<<dim3(8,8),256,SPEC_SMEM_BYTES,s2>>>(s);
    finalize_kernel<<<1,64,0,s2>>>(rho, th);
    cudaEventRecord(e2, s2);

    // join, scan (scaled), final accumulate mix
    cudaStreamWaitEvent(0, e1, 0);
    cudaStreamWaitEvent(0, e2, 0);
    scanA_kernel<<<256,64>>>();
    scanB_kernel<<<1,256>>>();
    scanC_kernel<<<256,64>>>(zdst);
    mix_mma_kernel<<<256,256,MIX_DSMEM>>>(zdst, Wbase + 262144, out, 2);
}